// round 11
// baseline (speedup 1.0000x reference)
#include <cuda_runtime.h>
#include <math.h>
#include <stdint.h>

#define Nn 50000
#define Ee 1600000
#define EPn 1650000   // Ee + Nn (self loops appended)
#define F 128         // H*C = 4*32
#define NBLK 49       // ceil(Nn/1024) for scan

// ---------------- scratch (static device memory; no allocation) ----------------
__device__ float    g_xl [(size_t)Nn * F];
__device__ float    g_xr [(size_t)Nn * F];
__device__ float    g_h  [(size_t)Nn * F];
__device__ int      g_count[Nn];
__device__ int      g_offs [Nn + 1];
__device__ int      g_cur  [Nn];
__device__ int      g_bsum [64];
__device__ float2   g_sedge[EPn];      // sorted (src_as_float_bits, weight)
__device__ float    g_partial[1024];
__device__ float    g_meanw;

// ---------------- mean(edge_weight), deterministic two-pass ----------------
__global__ void reduce_partial(const float* __restrict__ ew) {
    __shared__ float s[256];
    float acc = 0.f;
    for (int i = blockIdx.x * 256 + threadIdx.x; i < Ee; i += 1024 * 256)
        acc += ew[i];
    s[threadIdx.x] = acc;
    __syncthreads();
    for (int o = 128; o > 0; o >>= 1) {
        if (threadIdx.x < o) s[threadIdx.x] += s[threadIdx.x + o];
        __syncthreads();
    }
    if (threadIdx.x == 0) g_partial[blockIdx.x] = s[0];
}

__global__ void reduce_final() {
    __shared__ float s[1024];
    s[threadIdx.x] = g_partial[threadIdx.x];
    __syncthreads();
    for (int o = 512; o > 0; o >>= 1) {
        if (threadIdx.x < o) s[threadIdx.x] += s[threadIdx.x + o];
        __syncthreads();
    }
    if (threadIdx.x == 0) g_meanw = s[0] / (float)Ee;
}

// ---------------- CSR build: histogram -> scan -> scatter ----------------
__global__ void hist_kernel(const int* __restrict__ dst) {
    int e = blockIdx.x * 256 + threadIdx.x;
    if (e >= EPn) return;
    int d = (e < Ee) ? dst[e] : (e - Ee);
    atomicAdd(&g_count[d], 1);
}

__global__ void scan1_kernel() {      // grid NBLK, block 1024
    __shared__ int s[1024];
    int t = threadIdx.x;
    int i = blockIdx.x * 1024 + t;
    int v = (i < Nn) ? g_count[i] : 0;
    s[t] = v;
    __syncthreads();
    #pragma unroll
    for (int o = 1; o < 1024; o <<= 1) {
        int tmp = (t >= o) ? s[t - o] : 0;
        __syncthreads();
        s[t] += tmp;
        __syncthreads();
    }
    if (i < Nn) g_offs[i] = s[t] - v;           // exclusive within block
    if (t == 1023) g_bsum[blockIdx.x] = s[1023];
}

__global__ void scan2_kernel() {      // 1 block, 64 threads
    __shared__ int s[64];
    int t = threadIdx.x;
    int v = (t < NBLK) ? g_bsum[t] : 0;
    s[t] = v;
    __syncthreads();
    #pragma unroll
    for (int o = 1; o < 64; o <<= 1) {
        int tmp = (t >= o) ? s[t - o] : 0;
        __syncthreads();
        s[t] += tmp;
        __syncthreads();
    }
    g_bsum[t] = s[t] - v;                        // exclusive block offsets
}

__global__ void scan3_kernel() {
    int i = blockIdx.x * 256 + threadIdx.x;
    if (i < Nn) {
        int off = g_offs[i] + g_bsum[i >> 10];
        g_offs[i] = off;
        g_cur[i]  = off;
    }
    if (i == 0) g_offs[Nn] = EPn;
}

__global__ void scatter_kernel(const int* __restrict__ src,
                               const int* __restrict__ dst,
                               const float* __restrict__ ew) {
    int e = blockIdx.x * 256 + threadIdx.x;
    if (e >= EPn) return;
    int s, d; float w;
    if (e < Ee) { s = src[e]; d = dst[e]; w = ew[e]; }
    else        { s = e - Ee; d = s;      w = g_meanw; }
    int pos = atomicAdd(&g_cur[d], 1);
    g_sedge[pos] = make_float2(__int_as_float(s), w);
}

// ---------------- 3xTF32 tensor-core GEMM: C[M,128] = A[M,128] @ W[128,128] ----
// block = 256 threads (8 warps as 4x2), block tile 128x128, BK=16.
// smem tiles stored pre-swizzled in m16n8k8 fragment order; hi/lo tf32 split
// done in registers (Markidis 3-pass -> ~fp32 accuracy).

__device__ __forceinline__ uint32_t f2tf32(float x) {
    uint32_t r;
    asm("cvt.rna.tf32.f32 %0, %1;" : "=r"(r) : "f"(x));
    return r;
}

__device__ __forceinline__ void mma_tf32(float4& c, const uint32_t a[4],
                                         uint32_t b0, uint32_t b1) {
    asm volatile(
        "mma.sync.aligned.m16n8k8.row.col.f32.tf32.tf32.f32 "
        "{%0,%1,%2,%3}, {%4,%5,%6,%7}, {%8,%9}, {%0,%1,%2,%3};"
        : "+f"(c.x), "+f"(c.y), "+f"(c.z), "+f"(c.w)
        : "r"(a[0]), "r"(a[1]), "r"(a[2]), "r"(a[3]), "r"(b0), "r"(b1));
}

__global__ void __launch_bounds__(256)
gemm_tf32(const float* __restrict__ A, const float* __restrict__ W,
          float* __restrict__ C, int M)
{
    // sA: 16 a-tiles (ktile 2 x mtile 8), each 32 lanes x 4 regs
    // sB: 32 b-tiles (ktile 2 x ntile 16), each 32 lanes x 2 regs
    __shared__ float sA[2048];
    __shared__ float sB[2048];

    int t    = threadIdx.x;
    int lane = t & 31;
    int warp = t >> 5;
    int mt0  = (warp >> 1) * 2;     // warp's first mtile (0,2,4,6)
    int nt0  = (warp & 1) * 8;      // warp's first ntile (0 or 8)
    int bm0  = blockIdx.x * 128;

    float4 acc[2][8];
    #pragma unroll
    for (int i = 0; i < 2; ++i)
        #pragma unroll
        for (int j = 0; j < 8; ++j)
            acc[i][j] = make_float4(0.f, 0.f, 0.f, 0.f);

    for (int k0 = 0; k0 < 128; k0 += 16) {
        // ---- load + swizzle A tile (128 rows x 16 cols) ----
        #pragma unroll
        for (int u = 0; u < 2; ++u) {
            int id  = t * 2 + u;            // 0..511
            int row = id >> 2;              // 0..127
            int c4  = (id & 3) * 4;         // 0,4,8,12
            float4 v = make_float4(0.f, 0.f, 0.f, 0.f);
            if (bm0 + row < M)
                v = *(const float4*)&A[(size_t)(bm0 + row) * 128 + k0 + c4];
            int mtile = row >> 4, rl = row & 15;
            float vv[4] = {v.x, v.y, v.z, v.w};
            #pragma unroll
            for (int e = 0; e < 4; ++e) {
                int k = c4 + e;
                int ktile = k >> 3, kk = k & 7;
                int ln  = (rl & 7) * 4 + (kk & 3);
                int rg  = (rl >> 3) + 2 * (kk >> 2);
                sA[((ktile * 8 + mtile) * 32 + ln) * 4 + rg] = vv[e];
            }
        }
        // ---- load + swizzle B tile (16 rows x 128 cols of W) ----
        #pragma unroll
        for (int u = 0; u < 2; ++u) {
            int id   = t * 2 + u;           // 0..511
            int krow = id >> 5;             // 0..15
            int c4   = (id & 31) * 4;       // 0..124
            float4 v = *(const float4*)&W[(size_t)(k0 + krow) * 128 + c4];
            int ktile = krow >> 3, kk = krow & 7;
            float vv[4] = {v.x, v.y, v.z, v.w};
            #pragma unroll
            for (int e = 0; e < 4; ++e) {
                int n = c4 + e;
                int ntile = n >> 3, nn = n & 7;
                int ln = nn * 4 + (kk & 3);
                int rg = kk >> 2;
                sB[((ktile * 16 + ntile) * 32 + ln) * 2 + rg] = vv[e];
            }
        }
        __syncthreads();

        // ---- compute: 2 ktiles x (2 mtiles x 8 ntiles) x 3 passes ----
        #pragma unroll
        for (int kt = 0; kt < 2; ++kt) {
            uint32_t ahi[2][4], alo[2][4];
            #pragma unroll
            for (int i = 0; i < 2; ++i) {
                float4 ar = *(const float4*)&sA[((kt * 8 + mt0 + i) * 32 + lane) * 4];
                float av[4] = {ar.x, ar.y, ar.z, ar.w};
                #pragma unroll
                for (int r = 0; r < 4; ++r) {
                    uint32_t h = f2tf32(av[r]);
                    ahi[i][r] = h;
                    alo[i][r] = f2tf32(av[r] - __uint_as_float(h));
                }
            }
            #pragma unroll
            for (int j = 0; j < 8; ++j) {
                float2 br = *(const float2*)&sB[((kt * 16 + nt0 + j) * 32 + lane) * 2];
                uint32_t bh0 = f2tf32(br.x);
                uint32_t bh1 = f2tf32(br.y);
                uint32_t bl0 = f2tf32(br.x - __uint_as_float(bh0));
                uint32_t bl1 = f2tf32(br.y - __uint_as_float(bh1));
                #pragma unroll
                for (int i = 0; i < 2; ++i) {
                    mma_tf32(acc[i][j], ahi[i], bh0, bh1);   // hi*hi
                    mma_tf32(acc[i][j], ahi[i], bl0, bl1);   // hi*lo
                    mma_tf32(acc[i][j], alo[i], bh0, bh1);   // lo*hi
                }
            }
        }
        __syncthreads();
    }

    // ---- epilogue: write C frags ----
    int r  = lane >> 2;
    int cq = lane & 3;
    #pragma unroll
    for (int i = 0; i < 2; ++i) {
        int row0 = bm0 + (mt0 + i) * 16 + r;
        #pragma unroll
        for (int j = 0; j < 8; ++j) {
            int col = (nt0 + j) * 8 + cq * 2;
            float4 c = acc[i][j];
            if (row0 < M)
                *(float2*)&C[(size_t)row0 * 128 + col] = make_float2(c.x, c.y);
            if (row0 + 8 < M)
                *(float2*)&C[(size_t)(row0 + 8) * 128 + col] = make_float2(c.z, c.w);
        }
    }
}

// ---------------- CSR GAT layer: one warp per destination node ----------------
template<int LAYER>
__global__ void gat_csr_kernel(const float* __restrict__ xl,
                               const float* __restrict__ xr,
                               const float* __restrict__ We,
                               const float* __restrict__ att,
                               const float* __restrict__ bias,
                               float* __restrict__ outp)
{
    __shared__ float sWe[128], sAtt[128];
    int t = threadIdx.x;
    if (t < 128) { sWe[t] = We[t]; sAtt[t] = att[t]; }
    __syncthreads();

    int d    = (blockIdx.x * 256 + t) >> 5;
    int lane = t & 31;
    if (d >= Nn) return;

    int beg = g_offs[d], end = g_offs[d + 1];

    float4 b  = *(const float4*)(xr + (size_t)d * 128 + lane * 4);
    float4 we = *(const float4*)&sWe [lane * 4];
    float4 at = *(const float4*)&sAtt[lane * 4];

    float4 acc = make_float4(0.f, 0.f, 0.f, 0.f);
    float denom = 0.f;

    float2 eg = g_sedge[beg];
    float4 a  = *(const float4*)(xl + (size_t)__float_as_int(eg.x) * 128 + lane * 4);

    for (int i = beg; i < end; ++i) {
        float  w    = eg.y;
        float4 acur = a;
        if (i + 1 < end) {
            eg = g_sedge[i + 1];
            a  = *(const float4*)(xl + (size_t)__float_as_int(eg.x) * 128 + lane * 4);
        }
        float v0 = acur.x + b.x + w * we.x;
        float v1 = acur.y + b.y + w * we.y;
        float v2 = acur.z + b.z + w * we.z;
        float v3 = acur.w + b.w + w * we.w;
        v0 = v0 > 0.f ? v0 : 0.2f * v0;
        v1 = v1 > 0.f ? v1 : 0.2f * v1;
        v2 = v2 > 0.f ? v2 : 0.2f * v2;
        v3 = v3 > 0.f ? v3 : 0.2f * v3;
        float sum = v0 * at.x + v1 * at.y + v2 * at.z + v3 * at.w;

        sum += __shfl_xor_sync(0xffffffffu, sum, 1);
        sum += __shfl_xor_sync(0xffffffffu, sum, 2);
        sum += __shfl_xor_sync(0xffffffffu, sum, 4);

        float p = __expf(sum);
        denom += p;
        acc.x += p * acur.x;
        acc.y += p * acur.y;
        acc.z += p * acur.z;
        acc.w += p * acur.w;
    }

    float inv = 1.f / (denom + 1e-16f);
    float r0 = acc.x * inv, r1 = acc.y * inv, r2 = acc.z * inv, r3 = acc.w * inv;

    if (LAYER == 1) {
        float4 bb = *(const float4*)(bias + lane * 4);
        r0 += bb.x; r1 += bb.y; r2 += bb.z; r3 += bb.w;
        r0 = r0 > 0.f ? r0 : (__expf(r0) - 1.f);
        r1 = r1 > 0.f ? r1 : (__expf(r1) - 1.f);
        r2 = r2 > 0.f ? r2 : (__expf(r2) - 1.f);
        r3 = r3 > 0.f ? r3 : (__expf(r3) - 1.f);
        *(float4*)(outp + (size_t)d * 128 + lane * 4) = make_float4(r0, r1, r2, r3);
    } else {
        #pragma unroll
        for (int o = 8; o <= 16; o <<= 1) {
            r0 += __shfl_xor_sync(0xffffffffu, r0, o);
            r1 += __shfl_xor_sync(0xffffffffu, r1, o);
            r2 += __shfl_xor_sync(0xffffffffu, r2, o);
            r3 += __shfl_xor_sync(0xffffffffu, r3, o);
        }
        if (lane < 8) {
            float4 bb = *(const float4*)(bias + lane * 4);
            *(float4*)(outp + (size_t)d * 32 + lane * 4) =
                make_float4(0.25f * r0 + bb.x, 0.25f * r1 + bb.y,
                            0.25f * r2 + bb.z, 0.25f * r3 + bb.w);
        }
    }
}

// ---------------- launcher ----------------
extern "C" void kernel_launch(void* const* d_in, const int* in_sizes, int n_in,
                              void* d_out, int out_size)
{
    const float* x    = (const float*)d_in[0];
    const int*   ei   = (const int*)  d_in[1];
    const float* ew   = (const float*)d_in[2];
    const float* Wl1  = (const float*)d_in[3];
    const float* Wr1  = (const float*)d_in[4];
    const float* We1  = (const float*)d_in[5];
    const float* att1 = (const float*)d_in[6];
    const float* b1   = (const float*)d_in[7];
    const float* Wl2  = (const float*)d_in[8];
    const float* Wr2  = (const float*)d_in[9];
    const float* We2  = (const float*)d_in[10];
    const float* att2 = (const float*)d_in[11];
    const float* b2   = (const float*)d_in[12];
    float* out = (float*)d_out;

    const int* src = ei;
    const int* dst = ei + Ee;

    float *p_xl, *p_xr, *p_h;
    int* p_count;
    cudaGetSymbolAddress((void**)&p_xl,    g_xl);
    cudaGetSymbolAddress((void**)&p_xr,    g_xr);
    cudaGetSymbolAddress((void**)&p_h,     g_h);
    cudaGetSymbolAddress((void**)&p_count, g_count);

    const int gemmGrid = (Nn + 127) / 128;        // 391
    const int edgeGrid = (EPn + 255) / 256;
    const int nodeGrid = (Nn * 32 + 255) / 256;   // warp per node
    const int nGrid    = (Nn + 255) / 256;

    // mean edge weight
    reduce_partial<<<1024, 256>>>(ew);
    reduce_final<<<1, 1024>>>();

    // CSR build (shared by both layers)
    cudaMemsetAsync(p_count, 0, Nn * sizeof(int));
    hist_kernel<<<edgeGrid, 256>>>(dst);
    scan1_kernel<<<NBLK, 1024>>>();
    scan2_kernel<<<1, 64>>>();
    scan3_kernel<<<nGrid, 256>>>();
    scatter_kernel<<<edgeGrid, 256>>>(src, dst, ew);

    // ---- layer 1 ----
    gemm_tf32<<<gemmGrid, 256>>>(x, Wl1, p_xl, Nn);
    gemm_tf32<<<gemmGrid, 256>>>(x, Wr1, p_xr, Nn);
    gat_csr_kernel<1><<<nodeGrid, 256>>>(p_xl, p_xr, We1, att1, b1, p_h);

    // ---- layer 2 ----
    gemm_tf32<<<gemmGrid, 256>>>(p_h, Wl2, p_xl, Nn);
    gemm_tf32<<<gemmGrid, 256>>>(p_h, Wr2, p_xr, Nn);
    gat_csr_kernel<2><<<nodeGrid, 256>>>(p_xl, p_xr, We2, att2, b2, out);
}

// round 12
// speedup vs baseline: 1.0339x; 1.0339x over previous
#include <cuda_runtime.h>
#include <math.h>
#include <stdint.h>

#define Nn 50000
#define Ee 1600000
#define EPn 1650000   // Ee + Nn (self loops appended)
#define F 128         // H*C = 4*32
#define NBLK 49       // ceil(Nn/1024) for scan

// ---------------- scratch (static device memory; no allocation) ----------------
__device__ float    g_xl [(size_t)Nn * F];
__device__ float    g_xr [(size_t)Nn * F];
__device__ float    g_h  [(size_t)Nn * F];
__device__ int      g_count[Nn];
__device__ int      g_offs [Nn + 1];
__device__ int      g_cur  [Nn];
__device__ int      g_bsum [64];
__device__ float2   g_sedge[EPn];      // sorted (src_as_float_bits, weight)
__device__ float    g_partial[1024];
__device__ float    g_meanw;

// ---------------- mean(edge_weight), deterministic two-pass ----------------
__global__ void reduce_partial(const float* __restrict__ ew) {
    __shared__ float s[256];
    float acc = 0.f;
    for (int i = blockIdx.x * 256 + threadIdx.x; i < Ee; i += 1024 * 256)
        acc += ew[i];
    s[threadIdx.x] = acc;
    __syncthreads();
    for (int o = 128; o > 0; o >>= 1) {
        if (threadIdx.x < o) s[threadIdx.x] += s[threadIdx.x + o];
        __syncthreads();
    }
    if (threadIdx.x == 0) g_partial[blockIdx.x] = s[0];
}

__global__ void reduce_final() {
    __shared__ float s[1024];
    s[threadIdx.x] = g_partial[threadIdx.x];
    __syncthreads();
    for (int o = 512; o > 0; o >>= 1) {
        if (threadIdx.x < o) s[threadIdx.x] += s[threadIdx.x + o];
        __syncthreads();
    }
    if (threadIdx.x == 0) g_meanw = s[0] / (float)Ee;
}

// ---------------- CSR build: histogram -> scan -> scatter ----------------
__global__ void hist_kernel(const int* __restrict__ dst) {
    int e = blockIdx.x * 256 + threadIdx.x;
    if (e >= EPn) return;
    int d = (e < Ee) ? dst[e] : (e - Ee);
    atomicAdd(&g_count[d], 1);
}

__global__ void scan1_kernel() {      // grid NBLK, block 1024
    __shared__ int s[1024];
    int t = threadIdx.x;
    int i = blockIdx.x * 1024 + t;
    int v = (i < Nn) ? g_count[i] : 0;
    s[t] = v;
    __syncthreads();
    #pragma unroll
    for (int o = 1; o < 1024; o <<= 1) {
        int tmp = (t >= o) ? s[t - o] : 0;
        __syncthreads();
        s[t] += tmp;
        __syncthreads();
    }
    if (i < Nn) g_offs[i] = s[t] - v;           // exclusive within block
    if (t == 1023) g_bsum[blockIdx.x] = s[1023];
}

__global__ void scan2_kernel() {      // 1 block, 64 threads
    __shared__ int s[64];
    int t = threadIdx.x;
    int v = (t < NBLK) ? g_bsum[t] : 0;
    s[t] = v;
    __syncthreads();
    #pragma unroll
    for (int o = 1; o < 64; o <<= 1) {
        int tmp = (t >= o) ? s[t - o] : 0;
        __syncthreads();
        s[t] += tmp;
        __syncthreads();
    }
    g_bsum[t] = s[t] - v;                        // exclusive block offsets
}

__global__ void scan3_kernel() {
    int i = blockIdx.x * 256 + threadIdx.x;
    if (i < Nn) {
        int off = g_offs[i] + g_bsum[i >> 10];
        g_offs[i] = off;
        g_cur[i]  = off;
    }
    if (i == 0) g_offs[Nn] = EPn;
}

__global__ void scatter_kernel(const int* __restrict__ src,
                               const int* __restrict__ dst,
                               const float* __restrict__ ew) {
    int e = blockIdx.x * 256 + threadIdx.x;
    if (e >= EPn) return;
    int s, d; float w;
    if (e < Ee) { s = src[e]; d = dst[e]; w = ew[e]; }
    else        { s = e - Ee; d = s;      w = g_meanw; }
    int pos = atomicAdd(&g_cur[d], 1);
    g_sedge[pos] = make_float2(__int_as_float(s), w);
}

// ---------------- dual GEMM: C1 = A@W1, C2 = A@W2  (M x 128 @ 128 x 128) -----
// block = 256 threads = 8 warps, 32 rows/block; sA shared by both products.
__global__ void __launch_bounds__(256)
gemm_dual(const float* __restrict__ A,
          const float* __restrict__ W1, const float* __restrict__ W2,
          float* __restrict__ C1, float* __restrict__ C2, int M)
{
    __shared__ float sW1[32][128];
    __shared__ float sW2[32][128];
    __shared__ float sA[32][32];
    int t = threadIdx.x;
    int warp = t >> 5, lane = t & 31;
    int row0 = blockIdx.x * 32;
    float acc1[4][4] = {};
    float acc2[4][4] = {};

    for (int k0 = 0; k0 < 128; k0 += 32) {
        #pragma unroll
        for (int kr = warp; kr < 32; kr += 8) {
            *(float4*)&sW1[kr][lane * 4] = *(const float4*)&W1[(k0 + kr) * 128 + lane * 4];
            *(float4*)&sW2[kr][lane * 4] = *(const float4*)&W2[(k0 + kr) * 128 + lane * 4];
        }
        {
            int r  = t >> 3;
            int kk = (t & 7) * 4;
            int gr = row0 + r;
            float4 v = make_float4(0.f, 0.f, 0.f, 0.f);
            if (gr < M) v = *(const float4*)&A[(size_t)gr * 128 + k0 + kk];
            *(float4*)&sA[r][kk] = v;
        }
        __syncthreads();
        #pragma unroll
        for (int kk = 0; kk < 32; ++kk) {
            float u0 = sW1[kk][lane];
            float u1 = sW1[kk][32 + lane];
            float u2 = sW1[kk][64 + lane];
            float u3 = sW1[kk][96 + lane];
            float w0 = sW2[kk][lane];
            float w1 = sW2[kk][32 + lane];
            float w2 = sW2[kk][64 + lane];
            float w3 = sW2[kk][96 + lane];
            #pragma unroll
            for (int i = 0; i < 4; ++i) {
                float a = sA[warp * 4 + i][kk];
                acc1[i][0] += a * u0;
                acc1[i][1] += a * u1;
                acc1[i][2] += a * u2;
                acc1[i][3] += a * u3;
                acc2[i][0] += a * w0;
                acc2[i][1] += a * w1;
                acc2[i][2] += a * w2;
                acc2[i][3] += a * w3;
            }
        }
        __syncthreads();
    }
    #pragma unroll
    for (int i = 0; i < 4; ++i) {
        int gr = row0 + warp * 4 + i;
        if (gr < M) {
            #pragma unroll
            for (int j = 0; j < 4; ++j) {
                C1[(size_t)gr * 128 + j * 32 + lane] = acc1[i][j];
                C2[(size_t)gr * 128 + j * 32 + lane] = acc2[i][j];
            }
        }
    }
}

// ---------------- CSR GAT layer: one warp per destination node ----------------
// Lane owns features lane*4..lane*4+3 (head = lane>>3). Depth-2 software pipeline
// on the edge list + xl gathers; accumulation in registers; fused epilogue.
template<int LAYER>
__global__ void gat_csr_kernel(const float* __restrict__ xl,
                               const float* __restrict__ xr,
                               const float* __restrict__ We,
                               const float* __restrict__ att,
                               const float* __restrict__ bias,
                               float* __restrict__ outp)
{
    __shared__ float sWe[128], sAtt[128];
    int t = threadIdx.x;
    if (t < 128) { sWe[t] = We[t]; sAtt[t] = att[t]; }
    __syncthreads();

    int d    = (blockIdx.x * 256 + t) >> 5;
    int lane = t & 31;
    if (d >= Nn) return;

    int beg = g_offs[d], end = g_offs[d + 1];

    float4 b  = *(const float4*)(xr + (size_t)d * 128 + lane * 4);
    float4 we = *(const float4*)&sWe [lane * 4];
    float4 at = *(const float4*)&sAtt[lane * 4];

    float4 acc = make_float4(0.f, 0.f, 0.f, 0.f);
    float denom = 0.f;

    // depth-2 pipeline (every segment has >= 1 edge: the self-loop)
    float2 eg0 = g_sedge[beg];
    float4 a0  = *(const float4*)(xl + (size_t)__float_as_int(eg0.x) * 128 + lane * 4);
    float2 eg1 = make_float2(0.f, 0.f);
    float4 a1  = make_float4(0.f, 0.f, 0.f, 0.f);
    if (beg + 1 < end) {
        eg1 = g_sedge[beg + 1];
        a1  = *(const float4*)(xl + (size_t)__float_as_int(eg1.x) * 128 + lane * 4);
    }

    for (int i = beg; i < end; ++i) {
        float  w    = eg0.y;
        float4 acur = a0;
        eg0 = eg1; a0 = a1;
        if (i + 2 < end) {
            eg1 = g_sedge[i + 2];
            a1  = *(const float4*)(xl + (size_t)__float_as_int(eg1.x) * 128 + lane * 4);
        }

        float v0 = acur.x + b.x + w * we.x;
        float v1 = acur.y + b.y + w * we.y;
        float v2 = acur.z + b.z + w * we.z;
        float v3 = acur.w + b.w + w * we.w;
        v0 = v0 > 0.f ? v0 : 0.2f * v0;          // leaky_relu 0.2
        v1 = v1 > 0.f ? v1 : 0.2f * v1;
        v2 = v2 > 0.f ? v2 : 0.2f * v2;
        v3 = v3 > 0.f ? v3 : 0.2f * v3;
        float sum = v0 * at.x + v1 * at.y + v2 * at.z + v3 * at.w;

        // reduce within 8-lane head group; all 8 lanes end with the head logit
        sum += __shfl_xor_sync(0xffffffffu, sum, 1);
        sum += __shfl_xor_sync(0xffffffffu, sum, 2);
        sum += __shfl_xor_sync(0xffffffffu, sum, 4);

        float p = __expf(sum);
        denom += p;
        acc.x += p * acur.x;
        acc.y += p * acur.y;
        acc.z += p * acur.z;
        acc.w += p * acur.w;
    }

    float inv = 1.f / (denom + 1e-16f);
    float r0 = acc.x * inv, r1 = acc.y * inv, r2 = acc.z * inv, r3 = acc.w * inv;

    if (LAYER == 1) {
        float4 bb = *(const float4*)(bias + lane * 4);
        r0 += bb.x; r1 += bb.y; r2 += bb.z; r3 += bb.w;
        r0 = r0 > 0.f ? r0 : (__expf(r0) - 1.f);   // ELU
        r1 = r1 > 0.f ? r1 : (__expf(r1) - 1.f);
        r2 = r2 > 0.f ? r2 : (__expf(r2) - 1.f);
        r3 = r3 > 0.f ? r3 : (__expf(r3) - 1.f);
        *(float4*)(outp + (size_t)d * 128 + lane * 4) = make_float4(r0, r1, r2, r3);
    } else {
        // mean over 4 heads: channel c = (lane&7)*4+j lives in lanes differing by bits 3,4
        #pragma unroll
        for (int o = 8; o <= 16; o <<= 1) {
            r0 += __shfl_xor_sync(0xffffffffu, r0, o);
            r1 += __shfl_xor_sync(0xffffffffu, r1, o);
            r2 += __shfl_xor_sync(0xffffffffu, r2, o);
            r3 += __shfl_xor_sync(0xffffffffu, r3, o);
        }
        if (lane < 8) {
            float4 bb = *(const float4*)(bias + lane * 4);
            *(float4*)(outp + (size_t)d * 32 + lane * 4) =
                make_float4(0.25f * r0 + bb.x, 0.25f * r1 + bb.y,
                            0.25f * r2 + bb.z, 0.25f * r3 + bb.w);
        }
    }
}

// ---------------- launcher ----------------
extern "C" void kernel_launch(void* const* d_in, const int* in_sizes, int n_in,
                              void* d_out, int out_size)
{
    const float* x    = (const float*)d_in[0];
    const int*   ei   = (const int*)  d_in[1];
    const float* ew   = (const float*)d_in[2];
    const float* Wl1  = (const float*)d_in[3];
    const float* Wr1  = (const float*)d_in[4];
    const float* We1  = (const float*)d_in[5];
    const float* att1 = (const float*)d_in[6];
    const float* b1   = (const float*)d_in[7];
    const float* Wl2  = (const float*)d_in[8];
    const float* Wr2  = (const float*)d_in[9];
    const float* We2  = (const float*)d_in[10];
    const float* att2 = (const float*)d_in[11];
    const float* b2   = (const float*)d_in[12];
    float* out = (float*)d_out;

    const int* src = ei;
    const int* dst = ei + Ee;

    float *p_xl, *p_xr, *p_h;
    int* p_count;
    cudaGetSymbolAddress((void**)&p_xl,    g_xl);
    cudaGetSymbolAddress((void**)&p_xr,    g_xr);
    cudaGetSymbolAddress((void**)&p_h,     g_h);
    cudaGetSymbolAddress((void**)&p_count, g_count);

    const int gemmGrid = (Nn + 31) / 32;          // 1563
    const int edgeGrid = (EPn + 255) / 256;
    const int nodeGrid = (Nn * 32 + 255) / 256;   // warp per node
    const int nGrid    = (Nn + 255) / 256;

    // mean edge weight
    reduce_partial<<<1024, 256>>>(ew);
    reduce_final<<<1, 1024>>>();

    // CSR build (shared by both layers)
    cudaMemsetAsync(p_count, 0, Nn * sizeof(int));
    hist_kernel<<<edgeGrid, 256>>>(dst);
    scan1_kernel<<<NBLK, 1024>>>();
    scan2_kernel<<<1, 64>>>();
    scan3_kernel<<<nGrid, 256>>>();
    scatter_kernel<<<edgeGrid, 256>>>(src, dst, ew);

    // ---- layer 1 ----
    gemm_dual<<<gemmGrid, 256>>>(x, Wl1, Wr1, p_xl, p_xr, Nn);
    gat_csr_kernel<1><<<nodeGrid, 256>>>(p_xl, p_xr, We1, att1, b1, p_h);

    // ---- layer 2 ----
    gemm_dual<<<gemmGrid, 256>>>(p_h, Wl2, Wr2, p_xl, p_xr, Nn);
    gat_csr_kernel<2><<<nodeGrid, 256>>>(p_xl, p_xr, We2, att2, b2, out);
}